// round 12
// baseline (speedup 1.0000x reference)
#include <cuda_runtime.h>

#define BB      512
#define INF     512
#define OUTF    64
#define KK      16
#define NN      1024   // OUTF * KK
#define OUTCOLS 576    // INF + OUTF
#define THRESH  120.0f
#define QCAP    4096

typedef unsigned long long ull;

// Scratch (static device allocs are allowed).
__device__ float g_M[BB * NN];              // 2MB: M = x @ T
__device__ float g_G[OUTF * BB * 8];        // 1MB: 8 group-sums per (o,i)

#define FMA2D(d, a, b, c) \
    asm("fma.rn.f32x2 %0, %1, %2, %3;" : "=l"(d) : "l"(a), "l"(b), "l"(c))
#define ADD2(d, a, b) \
    asm("add.rn.f32x2 %0, %1, %2;" : "=l"(d) : "l"(a), "l"(b))

__device__ __forceinline__ void mma_tf32(float* c, const unsigned* a, const unsigned* b) {
    asm("mma.sync.aligned.m16n8k8.row.col.f32.tf32.tf32.f32 "
        "{%0,%1,%2,%3}, {%4,%5,%6,%7}, {%8,%9}, {%0,%1,%2,%3};"
        : "+f"(c[0]), "+f"(c[1]), "+f"(c[2]), "+f"(c[3])
        : "r"(a[0]), "r"(a[1]), "r"(a[2]), "r"(a[3]), "r"(b[0]), "r"(b[1]));
}

__device__ __forceinline__ void cp16(void* smem_dst, const void* gmem_src) {
    unsigned s = (unsigned)__cvta_generic_to_shared(smem_dst);
    asm volatile("cp.async.cg.shared.global [%0], [%1], 16;" :: "r"(s), "l"(gmem_src));
}

// ---------------------------------------------------------------------------
// GEMM via tf32 tensor cores, 3-stage cp.async pipeline.
// M = x(512x512) @ T(512x1024). Block 128 thr (4 warps, 2x2),
// tile 32x64, warp tile m16 x n32, k-tile 32. Grid (16,16) = 256 blocks.
// Epilogue writes g_M + group sums g_G; zero-inits out[:,512:576].
// ---------------------------------------------------------------------------
__global__ __launch_bounds__(128) void gemm_tc(const float* __restrict__ x,
                                               const float* __restrict__ T,
                                               float* __restrict__ out) {
    __shared__ float As[3][32][36];   // [stage][row][k], pad 36
    __shared__ float Bs[3][32][72];   // [stage][k][n],  pad 72

    const int tid  = threadIdx.x;
    const int warp = tid >> 5;
    const int lane = tid & 31;
    const int wm   = warp & 1;     // m half
    const int wn   = warp >> 1;    // n half
    const int tg   = lane >> 2;    // 0..7
    const int tig  = lane & 3;     // 0..3

    const int rowBase = blockIdx.y * 32;
    const int colBase = blockIdx.x * 64;

    // Zero-init the o_b region of out (32768 elems = 256 blocks x 128 thr).
    {
        int idx = (blockIdx.y * 16 + blockIdx.x) * 128 + tid;
        out[(idx >> 6) * OUTCOLS + INF + (idx & 63)] = 0.f;
    }

    const int ar0 = tid >> 3;            // A row  (0..15)
    const int ak0 = (tid & 7) * 4;       // A k-quad
    const int br0 = tid >> 4;            // B k row (0..7)
    const int bn0 = (tid & 15) * 4;      // B n-quad

#define ISSUE_TILE(st, k0)                                                        \
    do {                                                                          \
        cp16(&As[st][ar0][ak0],      &x[(rowBase + ar0) * INF + (k0) + ak0]);     \
        cp16(&As[st][ar0 + 16][ak0], &x[(rowBase + ar0 + 16) * INF + (k0) + ak0]);\
        cp16(&Bs[st][br0][bn0],      &T[((k0) + br0) * NN + colBase + bn0]);      \
        cp16(&Bs[st][br0 + 8][bn0],  &T[((k0) + br0 + 8) * NN + colBase + bn0]);  \
        cp16(&Bs[st][br0 + 16][bn0], &T[((k0) + br0 + 16) * NN + colBase + bn0]); \
        cp16(&Bs[st][br0 + 24][bn0], &T[((k0) + br0 + 24) * NN + colBase + bn0]); \
        asm volatile("cp.async.commit_group;");                                   \
    } while (0)

    ISSUE_TILE(0, 0);
    ISSUE_TILE(1, 32);

    float acc[4][4];
#pragma unroll
    for (int nt = 0; nt < 4; ++nt)
#pragma unroll
        for (int q = 0; q < 4; ++q) acc[nt][q] = 0.f;

    for (int kt = 0; kt < 16; ++kt) {
        asm volatile("cp.async.wait_group 1;");
        __syncthreads();
        const int st = kt % 3;

        // Refill stage (kt+2)%3 == (kt-1)%3 BEFORE compute: its readers all
        // passed the barrier above; issuing early lengthens the async lead.
        if (kt < 14) {
            const int stn = (kt + 2) % 3;
            const int k0n = (kt + 2) * 32;
            ISSUE_TILE(stn, k0n);
        }

#pragma unroll
        for (int ks = 0; ks < 32; ks += 8) {
            unsigned a[4], b[4][2];
            int rowA = wm * 16 + tg;
            a[0] = __float_as_uint(As[st][rowA][ks + tig]);
            a[1] = __float_as_uint(As[st][rowA + 8][ks + tig]);
            a[2] = __float_as_uint(As[st][rowA][ks + tig + 4]);
            a[3] = __float_as_uint(As[st][rowA + 8][ks + tig + 4]);
#pragma unroll
            for (int nt = 0; nt < 4; ++nt) {
                int colB = wn * 32 + nt * 8 + tg;
                b[nt][0] = __float_as_uint(Bs[st][ks + tig][colB]);
                b[nt][1] = __float_as_uint(Bs[st][ks + tig + 4][colB]);
            }
#pragma unroll
            for (int nt = 0; nt < 4; ++nt)
                mma_tf32(acc[nt], a, b[nt]);
        }
    }
#undef ISSUE_TILE

    // Epilogue: g_M + adjacent-pair group sums g_G.
#pragma unroll
    for (int nt = 0; nt < 4; ++nt) {
        int row0 = rowBase + wm * 16 + tg;
        int col0 = colBase + wn * 32 + nt * 8 + tig * 2;
        int o = col0 >> 4;
        int g = (col0 & 15) >> 1;
        *(float2*)&g_M[row0 * NN + col0]       = make_float2(acc[nt][0], acc[nt][1]);
        *(float2*)&g_M[(row0 + 8) * NN + col0] = make_float2(acc[nt][2], acc[nt][3]);
        g_G[((o << 9) + row0) * 8 + g]     = acc[nt][0] + acc[nt][1];
        g_G[((o << 9) + row0 + 8) * 8 + g] = acc[nt][2] + acc[nt][3];
    }
}

// ---------------------------------------------------------------------------
// Fused filter + exact via block-cooperative worklist. Grid (65, 8), 512 thr.
//   o < 64 : block (o, ec): i = tid, j in [ec*64, ec*64+64), j > i only.
//            Dense lb filter -> survivors pushed to smem queue -> barrier ->
//            whole block drains the queue (1 pair/thread), exact exp(-L1),
//            atomicAdd both out[i,o] and out[j,o].
//   o == 64: copy x rows into out[:, 0:512].
// ---------------------------------------------------------------------------
__global__ __launch_bounds__(512) void stage12(const float* __restrict__ x,
                                               float* __restrict__ out) {
    __shared__ __align__(16) ull   sG[64 * 4];    // 2 KB: group sums (packed)
    __shared__ __align__(16) float sM[64 * KK];   // 4 KB: M j-tile
    __shared__ int   qn;
    __shared__ short2 queue[QCAP];                // 16 KB

    const int o   = blockIdx.x;
    const int ec  = blockIdx.y;
    const int tid = threadIdx.x;

    if (o == OUTF) {
        int base = ec * 64;
#pragma unroll
        for (int t = tid; t < 64 * (INF / 4); t += 512) {
            int r = t >> 7;
            int c = t & 127;
            float4 v = *(const float4*)&x[(base + r) * INF + c * 4];
            *(float4*)&out[(base + r) * OUTCOLS + c * 4] = v;
        }
        return;
    }

    const int jbase = ec * 64;
    const int i     = tid;
    const int lim   = i - jbase;   // bits jj <= lim cleared (keep j > i)

    if (tid == 0) qn = 0;
    if (tid < 128) {
        int r = tid >> 1;
        int h = tid & 1;
        *(float4*)&sG[r * 4 + h * 2] =
            *(const float4*)&g_G[((o << 9) + jbase + r) * 8 + h * 4];
    } else if (tid < 384) {
        int t = tid - 128;           // 0..255
        int r = t >> 2;
        int q = t & 3;
        *(float4*)&sM[r * KK + q * 4] =
            *(const float4*)&g_M[(jbase + r) * NN + o * KK + q * 4];
    }

    ull gi[4];
    {
        const ulonglong2* p = (const ulonglong2*)&g_G[((o << 9) + i) * 8];
        ulonglong2 v0 = p[0], v1 = p[1];
        gi[0] = v0.x; gi[1] = v0.y; gi[2] = v1.x; gi[3] = v1.y;
    }
    __syncthreads();

    const ull NEG1  = 0xBF800000BF800000ULL;
    const ull AMASK = 0x7FFFFFFF7FFFFFFFULL;

    ull msk = 0;
    if (lim < 63) {
#pragma unroll
        for (int jj = 0; jj < 64; ++jj) {
            const ulonglong2* p = (const ulonglong2*)&sG[jj * 4];
            ulonglong2 v0 = p[0], v1 = p[1];

            ull d0, d1, d2, d3;
            FMA2D(d0, v0.x, NEG1, gi[0]);
            FMA2D(d1, v0.y, NEG1, gi[1]);
            FMA2D(d2, v1.x, NEG1, gi[2]);
            FMA2D(d3, v1.y, NEG1, gi[3]);
            d0 &= AMASK; d1 &= AMASK; d2 &= AMASK; d3 &= AMASK;

            ull s0, s1, t;
            ADD2(s0, d0, d1);
            ADD2(s1, d2, d3);
            ADD2(t, s0, s1);

            float lb = __uint_as_float((unsigned)t) + __uint_as_float((unsigned)(t >> 32));
            if (lb < THRESH) msk |= (1ULL << jj);
        }
        if (lim >= 0) msk &= ~((2ULL << lim) - 1ULL);
    }

    // Push survivors (i, jj) into the block queue.
    if (msk) {
        int n = __popcll(msk);
        int pos = atomicAdd(&qn, n);
        while (msk) {
            int bit = __ffsll((long long)msk) - 1;
            msk &= msk - 1;
            if (pos < QCAP) queue[pos] = make_short2((short)i, (short)bit);
            ++pos;
        }
    }
    __syncthreads();

    // Cooperative drain: one pair per thread, balanced across the block.
    const int total = (qn < QCAP) ? qn : QCAP;
    for (int t = tid; t < total; t += 512) {
        const int pi = queue[t].x;
        const int jj = queue[t].y;
        const int j  = jbase + jj;

        const float4* ri = (const float4*)&g_M[pi * NN + o * KK];
        float4 a = ri[0], b = ri[1], c = ri[2], d = ri[3];
        const float4* rj = (const float4*)&sM[jj * KK];
        float4 e = rj[0], f = rj[1], g = rj[2], h = rj[3];

        float norm =
            fabsf(a.x - e.x) + fabsf(a.y - e.y) + fabsf(a.z - e.z) + fabsf(a.w - e.w) +
            fabsf(b.x - f.x) + fabsf(b.y - f.y) + fabsf(b.z - f.z) + fabsf(b.w - f.w) +
            fabsf(c.x - g.x) + fabsf(c.y - g.y) + fabsf(c.z - g.z) + fabsf(c.w - g.w) +
            fabsf(d.x - h.x) + fabsf(d.y - h.y) + fabsf(d.z - h.z) + fabsf(d.w - h.w);

        float ev = __expf(-norm);
        if (ev != 0.f) {
            atomicAdd(&out[pi * OUTCOLS + INF + o], ev);
            atomicAdd(&out[j * OUTCOLS + INF + o], ev);
        }
    }
}

extern "C" void kernel_launch(void* const* d_in, const int* in_sizes, int n_in,
                              void* d_out, int out_size) {
    const float* x = (const float*)d_in[0];
    const float* T = (const float*)d_in[1];
    float* out = (float*)d_out;

    gemm_tc<<<dim3(NN / 64, BB / 32), 128>>>(x, T, out);
    stage12<<<dim3(OUTF + 1, 8), 512>>>(x, out);
}

// round 13
// speedup vs baseline: 1.0736x; 1.0736x over previous
#include <cuda_runtime.h>

#define BB      512
#define INF     512
#define OUTF    64
#define KK      16
#define NN      1024   // OUTF * KK
#define OUTCOLS 576    // INF + OUTF
#define THRESH  120.0f

typedef unsigned long long ull;

// Scratch (static device allocs are allowed).
__device__ float g_M[BB * NN];              // 2MB: M = x @ T
__device__ float g_G[OUTF * BB * 8];        // 1MB: 8 group-sums per (o,i)
__device__ ull   g_mask[OUTF * 8 * BB];     // 2MB: survivor bitmasks (j>i only)

#define FMA2D(d, a, b, c) \
    asm("fma.rn.f32x2 %0, %1, %2, %3;" : "=l"(d) : "l"(a), "l"(b), "l"(c))
#define ADD2(d, a, b) \
    asm("add.rn.f32x2 %0, %1, %2;" : "=l"(d) : "l"(a), "l"(b))

__device__ __forceinline__ void mma_tf32(float* c, const unsigned* a, const unsigned* b) {
    asm("mma.sync.aligned.m16n8k8.row.col.f32.tf32.tf32.f32 "
        "{%0,%1,%2,%3}, {%4,%5,%6,%7}, {%8,%9}, {%0,%1,%2,%3};"
        : "+f"(c[0]), "+f"(c[1]), "+f"(c[2]), "+f"(c[3])
        : "r"(a[0]), "r"(a[1]), "r"(a[2]), "r"(a[3]), "r"(b[0]), "r"(b[1]));
}

__device__ __forceinline__ void cp16(void* smem_dst, const void* gmem_src) {
    unsigned s = (unsigned)__cvta_generic_to_shared(smem_dst);
    asm volatile("cp.async.cg.shared.global [%0], [%1], 16;" :: "r"(s), "l"(gmem_src));
}

// ---------------------------------------------------------------------------
// GEMM via tf32 tensor cores, 3-stage cp.async pipeline, 8 warps/block.
// M = x(512x512) @ T(512x1024). Block 256 thr (8 warps, 2m x 4n),
// tile 32x64, warp tile m16 x n16, k-tile 32. Grid (16,16) = 256 blocks.
// Epilogue writes g_M + group sums g_G; zero-inits out[:,512:576].
// ---------------------------------------------------------------------------
__global__ __launch_bounds__(256) void gemm_tc(const float* __restrict__ x,
                                               const float* __restrict__ T,
                                               float* __restrict__ out) {
    __shared__ float As[3][32][36];   // [stage][row][k], pad 36
    __shared__ float Bs[3][32][72];   // [stage][k][n],  pad 72

    const int tid  = threadIdx.x;
    const int warp = tid >> 5;
    const int lane = tid & 31;
    const int wm   = warp & 1;     // m half (0..1)
    const int wn   = warp >> 1;    // n quarter (0..3)
    const int tg   = lane >> 2;    // 0..7
    const int tig  = lane & 3;     // 0..3

    const int rowBase = blockIdx.y * 32;
    const int colBase = blockIdx.x * 64;

    // Zero-init the o_b region of out (32768 elems; blocks 0..127 cover it).
    {
        int idx = (blockIdx.y * 16 + blockIdx.x) * 256 + tid;
        if (idx < BB * OUTF)
            out[(idx >> 6) * OUTCOLS + INF + (idx & 63)] = 0.f;
    }

    // cp.async chunk assignment: A 1 chunk/thr, B 2 chunks/thr.
    const int ar0 = tid >> 3;            // A row  (0..31)
    const int ak0 = (tid & 7) * 4;       // A k-quad
    const int br0 = tid >> 4;            // B k row (0..15)
    const int bn0 = (tid & 15) * 4;      // B n-quad

#define ISSUE_TILE(st, k0)                                                        \
    do {                                                                          \
        cp16(&As[st][ar0][ak0],      &x[(rowBase + ar0) * INF + (k0) + ak0]);     \
        cp16(&Bs[st][br0][bn0],      &T[((k0) + br0) * NN + colBase + bn0]);      \
        cp16(&Bs[st][br0 + 16][bn0], &T[((k0) + br0 + 16) * NN + colBase + bn0]); \
        asm volatile("cp.async.commit_group;");                                   \
    } while (0)

    ISSUE_TILE(0, 0);
    ISSUE_TILE(1, 32);

    float acc[2][4];
#pragma unroll
    for (int nt = 0; nt < 2; ++nt)
#pragma unroll
        for (int q = 0; q < 4; ++q) acc[nt][q] = 0.f;

    for (int kt = 0; kt < 16; ++kt) {
        asm volatile("cp.async.wait_group 1;");
        __syncthreads();
        const int st = kt % 3;

        // Refill stage (kt+2)%3 == (kt-1)%3 BEFORE compute (readers passed
        // the barrier above); issuing early lengthens the async lead.
        if (kt < 14) {
            const int stn = (kt + 2) % 3;
            const int k0n = (kt + 2) * 32;
            ISSUE_TILE(stn, k0n);
        }

#pragma unroll
        for (int ks = 0; ks < 32; ks += 8) {
            unsigned a[4], b[2][2];
            int rowA = wm * 16 + tg;
            a[0] = __float_as_uint(As[st][rowA][ks + tig]);
            a[1] = __float_as_uint(As[st][rowA + 8][ks + tig]);
            a[2] = __float_as_uint(As[st][rowA][ks + tig + 4]);
            a[3] = __float_as_uint(As[st][rowA + 8][ks + tig + 4]);
#pragma unroll
            for (int nt = 0; nt < 2; ++nt) {
                int colB = wn * 16 + nt * 8 + tg;
                b[nt][0] = __float_as_uint(Bs[st][ks + tig][colB]);
                b[nt][1] = __float_as_uint(Bs[st][ks + tig + 4][colB]);
            }
#pragma unroll
            for (int nt = 0; nt < 2; ++nt)
                mma_tf32(acc[nt], a, b[nt]);
        }
    }
#undef ISSUE_TILE

    // Epilogue: g_M + adjacent-pair group sums g_G.
#pragma unroll
    for (int nt = 0; nt < 2; ++nt) {
        int row0 = rowBase + wm * 16 + tg;
        int col0 = colBase + wn * 16 + nt * 8 + tig * 2;
        int o = col0 >> 4;
        int g = (col0 & 15) >> 1;
        *(float2*)&g_M[row0 * NN + col0]       = make_float2(acc[nt][0], acc[nt][1]);
        *(float2*)&g_M[(row0 + 8) * NN + col0] = make_float2(acc[nt][2], acc[nt][3]);
        g_G[((o << 9) + row0) * 8 + g]     = acc[nt][0] + acc[nt][1];
        g_G[((o << 9) + row0 + 8) * 8 + g] = acc[nt][2] + acc[nt][3];
    }
}

// ---------------------------------------------------------------------------
// Stage 1: symmetric lower-bound filter -> bitmask (bits only for j > i).
// 2-way interleaved jj loop for ILP. Grid (65, 8), 512 threads.
// o == 64: copy x rows into out[:, 0:512].
// ---------------------------------------------------------------------------
__global__ __launch_bounds__(512) void stage1_mask(const float* __restrict__ x,
                                                   float* __restrict__ out) {
    __shared__ __align__(16) ull sG[64 * 4];   // 64 j-rows x 4 packed group-pairs

    const int o   = blockIdx.x;
    const int ec  = blockIdx.y;
    const int tid = threadIdx.x;

    if (o == OUTF) {
        int base = ec * 64;
#pragma unroll
        for (int t = tid; t < 64 * (INF / 4); t += 512) {
            int r = t >> 7;
            int c = t & 127;
            float4 v = *(const float4*)&x[(base + r) * INF + c * 4];
            *(float4*)&out[(base + r) * OUTCOLS + c * 4] = v;
        }
        return;
    }

    const int jbase = ec * 64;
    const int i     = tid;
    const int lim   = i - jbase;   // bits jj <= lim cleared (keep j > i)

    if (tid < 128) {
        int r = tid >> 1;
        int h = tid & 1;
        *(float4*)&sG[r * 4 + h * 2] =
            *(const float4*)&g_G[((o << 9) + jbase + r) * 8 + h * 4];
    }

    ull gi[4];
    {
        const ulonglong2* p = (const ulonglong2*)&g_G[((o << 9) + i) * 8];
        ulonglong2 v0 = p[0], v1 = p[1];
        gi[0] = v0.x; gi[1] = v0.y; gi[2] = v1.x; gi[3] = v1.y;
    }
    __syncthreads();

    const ull NEG1  = 0xBF800000BF800000ULL;
    const ull AMASK = 0x7FFFFFFF7FFFFFFFULL;

#define LB_BODY(res, jj)                                                        \
    do {                                                                        \
        const ulonglong2* p = (const ulonglong2*)&sG[(jj) * 4];                 \
        ulonglong2 v0 = p[0], v1 = p[1];                                        \
        ull d0, d1, d2, d3;                                                     \
        FMA2D(d0, v0.x, NEG1, gi[0]);                                           \
        FMA2D(d1, v0.y, NEG1, gi[1]);                                           \
        FMA2D(d2, v1.x, NEG1, gi[2]);                                           \
        FMA2D(d3, v1.y, NEG1, gi[3]);                                           \
        d0 &= AMASK; d1 &= AMASK; d2 &= AMASK; d3 &= AMASK;                     \
        ull s0, s1, t;                                                          \
        ADD2(s0, d0, d1);                                                       \
        ADD2(s1, d2, d3);                                                       \
        ADD2(t, s0, s1);                                                        \
        res = __uint_as_float((unsigned)t) + __uint_as_float((unsigned)(t >> 32)); \
    } while (0)

    ull msk = 0;
    if (lim < 63) {
#pragma unroll
        for (int jj = 0; jj < 32; ++jj) {
            float lbA, lbB;            // two independent chains for ILP
            LB_BODY(lbA, jj);
            LB_BODY(lbB, jj + 32);
            if (lbA < THRESH) msk |= (1ULL << jj);
            if (lbB < THRESH) msk |= (1ULL << (jj + 32));
        }
        if (lim >= 0) msk &= ~((2ULL << lim) - 1ULL);
    }
#undef LB_BODY

    g_mask[(o * 8 + ec) * 512 + i] = msk;
}

// ---------------------------------------------------------------------------
// Stage 2: one thread per mask word; exact exp(-L1) for survivors,
// added to BOTH out[i,o] and out[j,o] (j > i). Grid 1024 x 256.
// ---------------------------------------------------------------------------
__global__ __launch_bounds__(256) void stage2_exact(float* __restrict__ out) {
    const int widx = blockIdx.x * 256 + threadIdx.x;   // 0..262143
    ull w = g_mask[widx];
    if (!w) return;

    const int o  = widx >> 12;
    const int ec = (widx >> 9) & 7;
    const int i  = widx & 511;

    const float4* ri = (const float4*)&g_M[i * NN + o * KK];
    float4 a = ri[0], b = ri[1], c = ri[2], d = ri[3];

    float acc = 0.f;
    while (w) {
        int bit = __ffsll((long long)w) - 1;
        w &= w - 1;
        int j = ec * 64 + bit;

        const float4* rj = (const float4*)&g_M[j * NN + o * KK];
        float4 e = rj[0], f = rj[1], g = rj[2], h = rj[3];

        float norm =
            fabsf(a.x - e.x) + fabsf(a.y - e.y) + fabsf(a.z - e.z) + fabsf(a.w - e.w) +
            fabsf(b.x - f.x) + fabsf(b.y - f.y) + fabsf(b.z - f.z) + fabsf(b.w - f.w) +
            fabsf(c.x - g.x) + fabsf(c.y - g.y) + fabsf(c.z - g.z) + fabsf(c.w - g.w) +
            fabsf(d.x - h.x) + fabsf(d.y - h.y) + fabsf(d.z - h.z) + fabsf(d.w - h.w);

        float ev = __expf(-norm);
        if (ev != 0.f) {
            acc += ev;
            atomicAdd(&out[j * OUTCOLS + INF + o], ev);
        }
    }
    if (acc != 0.f)
        atomicAdd(&out[i * OUTCOLS + INF + o], acc);
}

extern "C" void kernel_launch(void* const* d_in, const int* in_sizes, int n_in,
                              void* d_out, int out_size) {
    const float* x = (const float*)d_in[0];
    const float* T = (const float*)d_in[1];
    float* out = (float*)d_out;

    gemm_tc<<<dim3(NN / 64, BB / 32), 256>>>(x, T, out);
    stage1_mask<<<dim3(OUTF + 1, 8), 512>>>(x, out);
    stage2_exact<<<1024, 256>>>(out);
}

// round 15
// speedup vs baseline: 1.1176x; 1.0410x over previous
#include <cuda_runtime.h>
#include <cuda_bf16.h>

#define BB      512
#define INF     512
#define OUTF    64
#define KK      16
#define NN      1024   // OUTF * KK
#define OUTCOLS 576    // INF + OUTF
#define THRESH  120.0f

typedef unsigned long long ull;
typedef unsigned int uint;

// Scratch (static device allocs are allowed).
__device__ float g_M[BB * NN];                       // 2MB: M = x @ T (fp32)
__device__ float g_G[OUTF * BB * 8];                 // 1MB: 8 group-sums per (o,i)
__device__ ull   g_mask[OUTF * 8 * BB];              // 2MB: survivor bitmasks (j>i)
__device__ __align__(256) __nv_bfloat16 g_xb[BB * INF];    // x in bf16, K-major
__device__ __align__(256) __nv_bfloat16 g_Tb[NN * INF];    // T^T in bf16, K-major

#define FMA2D(d, a, b, c) \
    asm("fma.rn.f32x2 %0, %1, %2, %3;" : "=l"(d) : "l"(a), "l"(b), "l"(c))
#define ADD2(d, a, b) \
    asm("add.rn.f32x2 %0, %1, %2;" : "=l"(d) : "l"(a), "l"(b))

__device__ __forceinline__ void mma_bf16(float* c, const uint* a, const uint* b) {
    asm("mma.sync.aligned.m16n8k16.row.col.f32.bf16.bf16.f32 "
        "{%0,%1,%2,%3}, {%4,%5,%6,%7}, {%8,%9}, {%0,%1,%2,%3};"
        : "+f"(c[0]), "+f"(c[1]), "+f"(c[2]), "+f"(c[3])
        : "r"(a[0]), "r"(a[1]), "r"(a[2]), "r"(a[3]), "r"(b[0]), "r"(b[1]));
}

__device__ __forceinline__ void cp16(void* smem_dst, const void* gmem_src) {
    unsigned s = (unsigned)__cvta_generic_to_shared(smem_dst);
    asm volatile("cp.async.cg.shared.global [%0], [%1], 16;" :: "r"(s), "l"(gmem_src));
}

// ---------------------------------------------------------------------------
// Convert: x -> g_xb (bf16), T -> g_Tb (bf16, transposed to [n][k]),
// and zero-init out[:,512:576]. Grid 608 x 256.
//   bid < 512 : 32x32 transpose tile of T
//   bid < 576 : x convert
//   else      : zero o_b region
// ---------------------------------------------------------------------------
__global__ __launch_bounds__(256) void convert_k(const float* __restrict__ x,
                                                 const float* __restrict__ T,
                                                 float* __restrict__ out) {
    const int bid = blockIdx.x;
    const int tid = threadIdx.x;

    if (bid < 512) {
        __shared__ float sm[32][33];
        const int k0 = (bid >> 5) * 32;
        const int n0 = (bid & 31) * 32;
        {
            int r = tid >> 3, q = tid & 7;
            float4 v = *(const float4*)&T[(k0 + r) * NN + n0 + q * 4];
            sm[r][q * 4 + 0] = v.x; sm[r][q * 4 + 1] = v.y;
            sm[r][q * 4 + 2] = v.z; sm[r][q * 4 + 3] = v.w;
        }
        __syncthreads();
        {
            int rn = tid >> 3, q = tid & 7;       // out row n0+rn, k chunk q*4
            float f0 = sm[q * 4 + 0][rn], f1 = sm[q * 4 + 1][rn];
            float f2 = sm[q * 4 + 2][rn], f3 = sm[q * 4 + 3][rn];
            uint u0 = (uint)__bfloat16_as_ushort(__float2bfloat16(f0)) |
                      ((uint)__bfloat16_as_ushort(__float2bfloat16(f1)) << 16);
            uint u1 = (uint)__bfloat16_as_ushort(__float2bfloat16(f2)) |
                      ((uint)__bfloat16_as_ushort(__float2bfloat16(f3)) << 16);
            *(uint2*)&g_Tb[(n0 + rn) * INF + k0 + q * 4] = make_uint2(u0, u1);
        }
    } else if (bid < 576) {
        int base = ((bid - 512) * 256 + tid) * 16;
#pragma unroll
        for (int c = 0; c < 4; ++c) {
            float4 v = *(const float4*)&x[base + c * 4];
            uint u0 = (uint)__bfloat16_as_ushort(__float2bfloat16(v.x)) |
                      ((uint)__bfloat16_as_ushort(__float2bfloat16(v.y)) << 16);
            uint u1 = (uint)__bfloat16_as_ushort(__float2bfloat16(v.z)) |
                      ((uint)__bfloat16_as_ushort(__float2bfloat16(v.w)) << 16);
            *(uint2*)&g_xb[base + c * 4] = make_uint2(u0, u1);
        }
    } else {
        int idx = (bid - 576) * 1024 + tid * 4;   // over 32768 o_b elems
        *(float4*)&out[(idx >> 6) * OUTCOLS + INF + (idx & 63)] =
            make_float4(0.f, 0.f, 0.f, 0.f);
    }
}

// ---------------------------------------------------------------------------
// GEMM via bf16 mma.sync.m16n8k16, 3-stage cp.async pipeline.
// M = xb(512x512) @ Tb^T -> g_M fp32. Block 128 thr (4 warps, 2x2),
// tile 32x64, warp tile m16 x n32, k-tile 32 (= 2 k16 steps).
// Grid (16,16) = 256 blocks. Epilogue writes g_M + group sums g_G.
// Smem rows stored as uints (bf16 pairs), pitch 20 -> conflict-free gathers.
// ---------------------------------------------------------------------------
__global__ __launch_bounds__(128) void gemm_bf16() {
    __shared__ uint As[3][32][20];   // [stage][m-row][k-pair], pitch 20
    __shared__ uint Bs[3][64][20];   // [stage][n-row][k-pair], pitch 20

    const int tid  = threadIdx.x;
    const int warp = tid >> 5;
    const int lane = tid & 31;
    const int wm   = warp & 1;     // m half
    const int wn   = warp >> 1;    // n half
    const int tg   = lane >> 2;    // 0..7
    const int tig  = lane & 3;     // 0..3

    const int rowBase = blockIdx.y * 32;
    const int colBase = blockIdx.x * 64;

    const int ar = tid >> 2;       // 0..31 (A m-row / B n-row pair)
    const int aq = tid & 3;        // 16B chunk within the 64B k-row

#define ISSUE_TILE(st, k0)                                                      \
    do {                                                                        \
        cp16(&As[st][ar][aq * 4],      &g_xb[(rowBase + ar) * INF + (k0) + aq * 8]); \
        cp16(&Bs[st][ar][aq * 4],      &g_Tb[(colBase + ar) * INF + (k0) + aq * 8]); \
        cp16(&Bs[st][ar + 32][aq * 4], &g_Tb[(colBase + ar + 32) * INF + (k0) + aq * 8]); \
        asm volatile("cp.async.commit_group;");                                 \
    } while (0)

    ISSUE_TILE(0, 0);
    ISSUE_TILE(1, 32);

    float acc[4][4];
#pragma unroll
    for (int nt = 0; nt < 4; ++nt)
#pragma unroll
        for (int q = 0; q < 4; ++q) acc[nt][q] = 0.f;

    for (int kt = 0; kt < 16; ++kt) {
        asm volatile("cp.async.wait_group 1;");
        __syncthreads();
        const int st = kt % 3;

        // Refill stage (kt+2)%3 == (kt-1)%3 before compute (readers passed
        // the barrier above); lengthens the async lead.
        if (kt < 14) {
            const int stn = (kt + 2) % 3;
            const int k0n = (kt + 2) * 32;
            ISSUE_TILE(stn, k0n);
        }

#pragma unroll
        for (int h = 0; h < 2; ++h) {       // two k16 steps per k-tile
            const int ko = h * 8;           // uint (bf16-pair) offset
            uint a[4], b[4][2];
            int rowA = wm * 16 + tg;
            a[0] = As[st][rowA][ko + tig];
            a[1] = As[st][rowA + 8][ko + tig];
            a[2] = As[st][rowA][ko + tig + 4];
            a[3] = As[st][rowA + 8][ko + tig + 4];
#pragma unroll
            for (int nt = 0; nt < 4; ++nt) {
                int n = wn * 32 + nt * 8 + tg;
                b[nt][0] = Bs[st][n][ko + tig];
                b[nt][1] = Bs[st][n][ko + tig + 4];
            }
#pragma unroll
            for (int nt = 0; nt < 4; ++nt)
                mma_bf16(acc[nt], a, b[nt]);
        }
    }
#undef ISSUE_TILE

    // Epilogue: g_M + adjacent-pair group sums g_G.
#pragma unroll
    for (int nt = 0; nt < 4; ++nt) {
        int row0 = rowBase + wm * 16 + tg;
        int col0 = colBase + wn * 32 + nt * 8 + tig * 2;
        int o = col0 >> 4;
        int g = (col0 & 15) >> 1;
        *(float2*)&g_M[row0 * NN + col0]       = make_float2(acc[nt][0], acc[nt][1]);
        *(float2*)&g_M[(row0 + 8) * NN + col0] = make_float2(acc[nt][2], acc[nt][3]);
        g_G[((o << 9) + row0) * 8 + g]     = acc[nt][0] + acc[nt][1];
        g_G[((o << 9) + row0 + 8) * 8 + g] = acc[nt][2] + acc[nt][3];
    }
}

// ---------------------------------------------------------------------------
// Stage 1: symmetric lower-bound filter -> bitmask (bits only for j > i).
// 2-way interleaved jj loop. Grid (65, 8), 512 threads.
// o == 64: copy x rows into out[:, 0:512].
// ---------------------------------------------------------------------------
__global__ __launch_bounds__(512) void stage1_mask(const float* __restrict__ x,
                                                   float* __restrict__ out) {
    __shared__ __align__(16) ull sG[64 * 4];

    const int o   = blockIdx.x;
    const int ec  = blockIdx.y;
    const int tid = threadIdx.x;

    if (o == OUTF) {
        int base = ec * 64;
#pragma unroll
        for (int t = tid; t < 64 * (INF / 4); t += 512) {
            int r = t >> 7;
            int c = t & 127;
            float4 v = *(const float4*)&x[(base + r) * INF + c * 4];
            *(float4*)&out[(base + r) * OUTCOLS + c * 4] = v;
        }
        return;
    }

    const int jbase = ec * 64;
    const int i     = tid;
    const int lim   = i - jbase;   // bits jj <= lim cleared (keep j > i)

    if (tid < 128) {
        int r = tid >> 1;
        int h = tid & 1;
        *(float4*)&sG[r * 4 + h * 2] =
            *(const float4*)&g_G[((o << 9) + jbase + r) * 8 + h * 4];
    }

    ull gi[4];
    {
        const ulonglong2* p = (const ulonglong2*)&g_G[((o << 9) + i) * 8];
        ulonglong2 v0 = p[0], v1 = p[1];
        gi[0] = v0.x; gi[1] = v0.y; gi[2] = v1.x; gi[3] = v1.y;
    }
    __syncthreads();

    const ull NEG1  = 0xBF800000BF800000ULL;
    const ull AMASK = 0x7FFFFFFF7FFFFFFFULL;

#define LB_BODY(res, jj)                                                        \
    do {                                                                        \
        const ulonglong2* p = (const ulonglong2*)&sG[(jj) * 4];                 \
        ulonglong2 v0 = p[0], v1 = p[1];                                        \
        ull d0, d1, d2, d3;                                                     \
        FMA2D(d0, v0.x, NEG1, gi[0]);                                           \
        FMA2D(d1, v0.y, NEG1, gi[1]);                                           \
        FMA2D(d2, v1.x, NEG1, gi[2]);                                           \
        FMA2D(d3, v1.y, NEG1, gi[3]);                                           \
        d0 &= AMASK; d1 &= AMASK; d2 &= AMASK; d3 &= AMASK;                     \
        ull s0, s1, t;                                                          \
        ADD2(s0, d0, d1);                                                       \
        ADD2(s1, d2, d3);                                                       \
        ADD2(t, s0, s1);                                                        \
        res = __uint_as_float((unsigned)t) + __uint_as_float((unsigned)(t >> 32)); \
    } while (0)

    ull msk = 0;
    if (lim < 63) {
#pragma unroll
        for (int jj = 0; jj < 32; ++jj) {
            float lbA, lbB;            // two independent chains for ILP
            LB_BODY(lbA, jj);
            LB_BODY(lbB, jj + 32);
            if (lbA < THRESH) msk |= (1ULL << jj);
            if (lbB < THRESH) msk |= (1ULL << (jj + 32));
        }
        if (lim >= 0) msk &= ~((2ULL << lim) - 1ULL);
    }
#undef LB_BODY

    g_mask[(o * 8 + ec) * 512 + i] = msk;
}

// ---------------------------------------------------------------------------
// Stage 2: one thread per mask word; exact exp(-L1) for survivors,
// added to BOTH out[i,o] and out[j,o] (j > i). Grid 1024 x 256.
// ---------------------------------------------------------------------------
__global__ __launch_bounds__(256) void stage2_exact(float* __restrict__ out) {
    const int widx = blockIdx.x * 256 + threadIdx.x;
    ull w = g_mask[widx];
    if (!w) return;

    const int o  = widx >> 12;
    const int ec = (widx >> 9) & 7;
    const int i  = widx & 511;

    const float4* ri = (const float4*)&g_M[i * NN + o * KK];
    float4 a = ri[0], b = ri[1], c = ri[2], d = ri[3];

    float acc = 0.f;
    while (w) {
        int bit = __ffsll((long long)w) - 1;
        w &= w - 1;
        int j = ec * 64 + bit;

        const float4* rj = (const float4*)&g_M[j * NN + o * KK];
        float4 e = rj[0], f = rj[1], g = rj[2], h = rj[3];

        float norm =
            fabsf(a.x - e.x) + fabsf(a.y - e.y) + fabsf(a.z - e.z) + fabsf(a.w - e.w) +
            fabsf(b.x - f.x) + fabsf(b.y - f.y) + fabsf(b.z - f.z) + fabsf(b.w - f.w) +
            fabsf(c.x - g.x) + fabsf(c.y - g.y) + fabsf(c.z - g.z) + fabsf(c.w - g.w) +
            fabsf(d.x - h.x) + fabsf(d.y - h.y) + fabsf(d.z - h.z) + fabsf(d.w - h.w);

        float ev = __expf(-norm);
        if (ev != 0.f) {
            acc += ev;
            atomicAdd(&out[j * OUTCOLS + INF + o], ev);
        }
    }
    if (acc != 0.f)
        atomicAdd(&out[i * OUTCOLS + INF + o], acc);
}

extern "C" void kernel_launch(void* const* d_in, const int* in_sizes, int n_in,
                              void* d_out, int out_size) {
    const float* x = (const float*)d_in[0];
    const float* T = (const float*)d_in[1];
    float* out = (float*)d_out;

    convert_k<<<608, 256>>>(x, T, out);
    gemm_bf16<<<dim3(NN / 64, BB / 32), 128>>>();
    stage1_mask<<<dim3(OUTF + 1, 8), 512>>>(x, out);
    stage2_exact<<<1024, 256>>>(out);
}